// round 1
// baseline (speedup 1.0000x reference)
#include <cuda_runtime.h>
#include <math.h>

#define BB 8
#define SS 1024
#define EE 1024
#define HH 8
#define HD 128
#define MM (BB*SS)

// Scratch (allocation-free: __device__ globals)
__device__ float g_wn[4L * EE * EE];            // normalized weights q,k,v,o
__device__ float g_qkv[3L * MM * EE];           // Q,K,V projections
__device__ float g_sc[(long)BB * HH * SS * SS]; // scores / attn (256 MB)
__device__ float g_ov[(long)MM * EE];           // attention output

// ---------------------------------------------------------------------------
// Weight normalization: wn = w * gain / (sqrt(fan_in)*EPS + ||row||)
// ---------------------------------------------------------------------------
__global__ void norm_w_kernel(const float* __restrict__ qw,
                              const float* __restrict__ kw,
                              const float* __restrict__ vw,
                              const float* __restrict__ ow,
                              const float* __restrict__ gain) {
    int mat = blockIdx.y;
    int row = blockIdx.x;
    const float* w = (mat == 0) ? qw : (mat == 1) ? kw : (mat == 2) ? vw : ow;
    const float* wr = w + (long)row * EE;
    __shared__ float red[256];
    float s = 0.f;
    for (int i = threadIdx.x; i < EE; i += 256) { float v = wr[i]; s += v * v; }
    red[threadIdx.x] = s; __syncthreads();
    for (int o = 128; o > 0; o >>= 1) {
        if (threadIdx.x < o) red[threadIdx.x] += red[threadIdx.x + o];
        __syncthreads();
    }
    float n = sqrtf(red[0]);
    float scale = gain[0] / (32.0f * 1e-4f + n);   // sqrt(1024)*EPS + n
    float* out = g_wn + (long)mat * EE * EE + (long)row * EE;
    for (int i = threadIdx.x; i < EE; i += 256) out[i] = wr[i] * scale;
}

// ---------------------------------------------------------------------------
// TN SGEMM: C[M,N] = A[M,K] @ B[N,K]^T   (both operands K-contiguous)
// 128x128x8 tile, 8x8 per thread, 256 threads.
// MODE 0: C = acc
// MODE 1: C = acc*alpha + X   (scores: scale + rel-pos bias, ldx separate)
// MODE 2: C = (acc + X) * 1/sqrt(2)   (mp_sum residual with t=0.5)
// Batch: z -> (zb = z/zdiv, zh = z%zdiv); offsets via per-operand strides.
// ---------------------------------------------------------------------------
template<int MODE>
__global__ __launch_bounds__(256) void sgemm_tn(
    const float* __restrict__ A, long sA1, long sA2,
    const float* __restrict__ Bw, long sB1, long sB2,
    float* __restrict__ C, long sC1, long sC2,
    const float* __restrict__ X, long sX1, long sX2,
    int lda, int ldb, int ldc, int ldx,
    int Kr, int zdiv, float alpha)
{
    constexpr int BK = 8;
    __shared__ float As[BK][128];
    __shared__ float Bs[BK][128];
    int z = blockIdx.z;
    int zb = z / zdiv, zh = z - zb * zdiv;
    A  += zb * sA1 + zh * sA2;
    Bw += zb * sB1 + zh * sB2;
    C  += zb * sC1 + zh * sC2;
    if (MODE != 0) X += zb * sX1 + zh * sX2;

    int bm = blockIdx.y * 128, bn = blockIdx.x * 128;
    int tid = threadIdx.x;
    int tx = tid & 15, ty = tid >> 4;
    int lr = tid >> 1;
    int lc = (tid & 1) * 4;

    float acc[8][8];
    #pragma unroll
    for (int i = 0; i < 8; i++)
        #pragma unroll
        for (int j = 0; j < 8; j++) acc[i][j] = 0.f;

    for (int k0 = 0; k0 < Kr; k0 += BK) {
        float4 a = *(const float4*)(A  + (long)(bm + lr) * lda + k0 + lc);
        float4 b = *(const float4*)(Bw + (long)(bn + lr) * ldb + k0 + lc);
        As[lc + 0][lr] = a.x; As[lc + 1][lr] = a.y; As[lc + 2][lr] = a.z; As[lc + 3][lr] = a.w;
        Bs[lc + 0][lr] = b.x; Bs[lc + 1][lr] = b.y; Bs[lc + 2][lr] = b.z; Bs[lc + 3][lr] = b.w;
        __syncthreads();
        #pragma unroll
        for (int kk = 0; kk < BK; kk++) {
            float ar[8], br[8];
            #pragma unroll
            for (int i = 0; i < 8; i++) ar[i] = As[kk][ty * 8 + i];
            #pragma unroll
            for (int j = 0; j < 8; j++) br[j] = Bs[kk][tx * 8 + j];
            #pragma unroll
            for (int i = 0; i < 8; i++)
                #pragma unroll
                for (int j = 0; j < 8; j++)
                    acc[i][j] = fmaf(ar[i], br[j], acc[i][j]);
        }
        __syncthreads();
    }

    #pragma unroll
    for (int i = 0; i < 8; i++) {
        int row = bm + ty * 8 + i;
        #pragma unroll
        for (int j = 0; j < 8; j += 4) {
            int col = bn + tx * 8 + j;
            float4 v;
            v.x = acc[i][j]; v.y = acc[i][j+1]; v.z = acc[i][j+2]; v.w = acc[i][j+3];
            if (MODE == 1) {
                float4 bq = *(const float4*)(X + (long)row * ldx + col);
                v.x = v.x * alpha + bq.x; v.y = v.y * alpha + bq.y;
                v.z = v.z * alpha + bq.z; v.w = v.w * alpha + bq.w;
            } else if (MODE == 2) {
                float4 rq = *(const float4*)(X + (long)row * ldx + col);
                const float c = 0.70710678118654752f;  // 0.5/sqrt(0.5)
                v.x = (v.x + rq.x) * c; v.y = (v.y + rq.y) * c;
                v.z = (v.z + rq.z) * c; v.w = (v.w + rq.w) * c;
            }
            *(float4*)(C + (long)row * ldc + col) = v;
        }
    }
}

// ---------------------------------------------------------------------------
// NN SGEMM: C[M,N] = A[M,K] @ B[K,N]  (for attn @ V, N=128)
// ---------------------------------------------------------------------------
__global__ __launch_bounds__(256) void sgemm_nn(
    const float* __restrict__ A, long sA1, long sA2,
    const float* __restrict__ Bm, long sB1, long sB2,
    float* __restrict__ C, long sC1, long sC2,
    int lda, int ldb, int ldc, int Kr, int zdiv)
{
    constexpr int BK = 8;
    __shared__ float As[BK][128];
    __shared__ float Bs[BK][128];
    int z = blockIdx.z;
    int zb = z / zdiv, zh = z - zb * zdiv;
    A  += zb * sA1 + zh * sA2;
    Bm += zb * sB1 + zh * sB2;
    C  += zb * sC1 + zh * sC2;

    int bm = blockIdx.y * 128, bn = blockIdx.x * 128;
    int tid = threadIdx.x;
    int tx = tid & 15, ty = tid >> 4;
    int lrA = tid >> 1, lcA = (tid & 1) * 4;
    int lrB = tid >> 5, lcB = (tid & 31) * 4;

    float acc[8][8];
    #pragma unroll
    for (int i = 0; i < 8; i++)
        #pragma unroll
        for (int j = 0; j < 8; j++) acc[i][j] = 0.f;

    for (int k0 = 0; k0 < Kr; k0 += BK) {
        float4 a = *(const float4*)(A  + (long)(bm + lrA) * lda + k0 + lcA);
        float4 b = *(const float4*)(Bm + (long)(k0 + lrB) * ldb + bn + lcB);
        As[lcA + 0][lrA] = a.x; As[lcA + 1][lrA] = a.y;
        As[lcA + 2][lrA] = a.z; As[lcA + 3][lrA] = a.w;
        *(float4*)(&Bs[lrB][lcB]) = b;
        __syncthreads();
        #pragma unroll
        for (int kk = 0; kk < BK; kk++) {
            float ar[8], br[8];
            #pragma unroll
            for (int i = 0; i < 8; i++) ar[i] = As[kk][ty * 8 + i];
            #pragma unroll
            for (int j = 0; j < 8; j++) br[j] = Bs[kk][tx * 8 + j];
            #pragma unroll
            for (int i = 0; i < 8; i++)
                #pragma unroll
                for (int j = 0; j < 8; j++)
                    acc[i][j] = fmaf(ar[i], br[j], acc[i][j]);
        }
        __syncthreads();
    }

    #pragma unroll
    for (int i = 0; i < 8; i++) {
        int row = bm + ty * 8 + i;
        #pragma unroll
        for (int j = 0; j < 8; j += 4) {
            int col = bn + tx * 8 + j;
            float4 v;
            v.x = acc[i][j]; v.y = acc[i][j+1]; v.z = acc[i][j+2]; v.w = acc[i][j+3];
            *(float4*)(C + (long)row * ldc + col) = v;
        }
    }
}

// ---------------------------------------------------------------------------
// Row softmax over last dim (1024), one block per row, in-place.
// ---------------------------------------------------------------------------
__global__ void softmax_kernel(float* __restrict__ sc) {
    long row = blockIdx.x;
    float4* p = (float4*)(sc + row * (long)SS);
    __shared__ float red[256];
    int t = threadIdx.x;
    float4 v = p[t];
    float mx = fmaxf(fmaxf(v.x, v.y), fmaxf(v.z, v.w));
    red[t] = mx; __syncthreads();
    for (int o = 128; o > 0; o >>= 1) {
        if (t < o) red[t] = fmaxf(red[t], red[t + o]);
        __syncthreads();
    }
    float m = red[0];
    __syncthreads();
    v.x = __expf(v.x - m); v.y = __expf(v.y - m);
    v.z = __expf(v.z - m); v.w = __expf(v.w - m);
    float s = v.x + v.y + v.z + v.w;
    red[t] = s; __syncthreads();
    for (int o = 128; o > 0; o >>= 1) {
        if (t < o) red[t] += red[t + o];
        __syncthreads();
    }
    float inv = 1.0f / red[0];
    v.x *= inv; v.y *= inv; v.z *= inv; v.w *= inv;
    p[t] = v;
}

// ---------------------------------------------------------------------------
// Launch
// ---------------------------------------------------------------------------
extern "C" void kernel_launch(void* const* d_in, const int* in_sizes, int n_in,
                              void* d_out, int out_size) {
    const float* query  = (const float*)d_in[0];
    const float* gain_s = (const float*)d_in[1];
    // d_in[2] = gain_t (unused: time_dim=0)
    const float* qw = (const float*)d_in[3];
    const float* kw = (const float*)d_in[4];
    const float* vw = (const float*)d_in[5];
    const float* ow = (const float*)d_in[6];
    const float* bias = (const float*)d_in[7];
    float* out = (float*)d_out;

    float *wn, *qkv, *sc, *ov;
    cudaGetSymbolAddress((void**)&wn,  g_wn);
    cudaGetSymbolAddress((void**)&qkv, g_qkv);
    cudaGetSymbolAddress((void**)&sc,  g_sc);
    cudaGetSymbolAddress((void**)&ov,  g_ov);

    // 1. Normalize the 4 weight matrices
    norm_w_kernel<<<dim3(EE, 4), 256>>>(qw, kw, vw, ow, gain_s);

    // 2. Q,K,V projections: qkv[z] = query @ wn[z]^T  (z = 0,1,2)
    sgemm_tn<0><<<dim3(EE/128, MM/128, 3), 256>>>(
        query, 0, 0,
        wn, (long)EE*EE, 0,
        qkv, (long)MM*EE, 0,
        (const float*)nullptr, 0, 0,
        EE, EE, EE, 0,
        EE, 1, 1.0f);

    // 3. scores = Q @ K^T / sqrt(hd) + rel_pos_bias   (z = b*H + h)
    sgemm_tn<1><<<dim3(SS/128, SS/128, BB*HH), 256>>>(
        qkv, (long)SS*EE, (long)HD,                     // Q
        qkv + (long)MM*EE, (long)SS*EE, (long)HD,       // K
        sc, (long)HH*SS*SS, (long)SS*SS,
        bias, 0, (long)SS*SS,
        EE, EE, SS, SS,
        HD, HH, 0.08838834764831845f);                  // 1/sqrt(128)

    // 4. softmax (in place)
    softmax_kernel<<<BB*HH*SS, 256>>>(sc);

    // 5. O = attn @ V   (per head, N=128)
    sgemm_nn<<<dim3(1, SS/128, BB*HH), 256>>>(
        sc, (long)HH*SS*SS, (long)SS*SS,
        qkv + 2L*MM*EE, (long)SS*EE, (long)HD,          // V
        ov, (long)SS*EE, (long)HD,
        SS, EE, EE, SS, HH);

    // 6. out = (query + O @ wn_o^T) * 1/sqrt(2)
    sgemm_tn<2><<<dim3(EE/128, MM/128, 1), 256>>>(
        ov, 0, 0,
        wn + 3L*EE*EE, 0, 0,
        out, 0, 0,
        query, 0, 0,
        EE, EE, EE, EE,
        EE, 1, 1.0f);
}

// round 4
// speedup vs baseline: 1.6927x; 1.6927x over previous
#include <cuda_runtime.h>
#include <cuda_bf16.h>
#include <cstdint>
#include <math.h>

#define BB 8
#define SS 1024
#define EE 1024
#define HH 8
#define HD 128
#define MM (BB*SS)

// Scratch (allocation-free: __device__ globals)
__device__ float g_wn[4L * EE * EE];            // normalized weights q,k,v,o
__device__ float g_qkv[3L * MM * EE];           // Q,K projections + V^T
__device__ float g_sc[(long)BB * HH * SS * SS]; // scores / attn (256 MB)
__device__ float g_ov[(long)MM * EE];           // attention output

// ===========================================================================
// helpers
// ===========================================================================
__device__ __forceinline__ uint32_t smem_u32(const void* p) {
    uint32_t a;
    asm("{ .reg .u64 t; cvta.to.shared.u64 t, %1; cvt.u32.u64 %0, t; }"
        : "=r"(a) : "l"(p));
    return a;
}
__device__ __forceinline__ void ldmat4(uint32_t* r, uint32_t addr) {
    asm volatile("ldmatrix.sync.aligned.m8n8.x4.shared.b16 {%0,%1,%2,%3}, [%4];"
                 : "=r"(r[0]), "=r"(r[1]), "=r"(r[2]), "=r"(r[3]) : "r"(addr));
}
__device__ __forceinline__ void mma16816(float* c, const uint32_t* a, const uint32_t* b) {
    asm volatile(
        "mma.sync.aligned.m16n8k16.row.col.f32.bf16.bf16.f32 "
        "{%0,%1,%2,%3}, {%4,%5,%6,%7}, {%8,%9}, {%0,%1,%2,%3};"
        : "+f"(c[0]), "+f"(c[1]), "+f"(c[2]), "+f"(c[3])
        : "r"(a[0]), "r"(a[1]), "r"(a[2]), "r"(a[3]), "r"(b[0]), "r"(b[1]));
}
__device__ __forceinline__ uint32_t pack_hi(float x, float y) {
    __nv_bfloat162 t;
    t.x = __float2bfloat16(x); t.y = __float2bfloat16(y);
    return *(uint32_t*)&t;
}
__device__ __forceinline__ uint32_t pack_lo(float x, float y) {
    __nv_bfloat16 hx = __float2bfloat16(x), hy = __float2bfloat16(y);
    __nv_bfloat162 t;
    t.x = __float2bfloat16(x - __bfloat162float(hx));
    t.y = __float2bfloat16(y - __bfloat162float(hy));
    return *(uint32_t*)&t;
}

// ===========================================================================
// Weight normalization: wn = w * gain / (sqrt(fan_in)*EPS + ||row||)
// ===========================================================================
__global__ void norm_w_kernel(const float* __restrict__ qw,
                              const float* __restrict__ kw,
                              const float* __restrict__ vw,
                              const float* __restrict__ ow,
                              const float* __restrict__ gain) {
    int mat = blockIdx.y;
    int row = blockIdx.x;
    const float* w = (mat == 0) ? qw : (mat == 1) ? kw : (mat == 2) ? vw : ow;
    const float* wr = w + (long)row * EE;
    __shared__ float red[256];
    float s = 0.f;
    for (int i = threadIdx.x; i < EE; i += 256) { float v = wr[i]; s += v * v; }
    red[threadIdx.x] = s; __syncthreads();
    for (int o = 128; o > 0; o >>= 1) {
        if (threadIdx.x < o) red[threadIdx.x] += red[threadIdx.x + o];
        __syncthreads();
    }
    float n = sqrtf(red[0]);
    float scale = gain[0] / (32.0f * 1e-4f + n);
    float* out = g_wn + (long)mat * EE * EE + (long)row * EE;
    for (int i = threadIdx.x; i < EE; i += 256) out[i] = wr[i] * scale;
}

// ===========================================================================
// mma.sync GEMM: D[M,N] = A[M,K] @ B[N,K]^T, fp32 in/out, split-bf16 (bf16x3):
//   D = Ah Bh^T + Ah Bl^T + Al Bh^T  (3 "planes" per real 32-wide K chunk;
//   the fp32 chunk is LDG'd once and converted per plane at STS time).
// CTA tile 128x128, 8 warps (4x2) of 32x64, BK=32, 2-stage smem.
// B tiles stored [n][k] K-contiguous -> ldmatrix NON-trans gives the
// .row.col B fragment directly (trans was the Round-3 bug).
// MODE 0: C = acc
// MODE 2: C = (acc + X) * (1/sqrt(2))   (mp_sum residual, t=0.5)
// MODE 3: transpose write: C as vt[b][h][d][s]
// ===========================================================================
template<int MODE>
__global__ __launch_bounds__(256) void mma_gemm(
    const float* __restrict__ A, long sA1, long sA2, int lda,
    const float* __restrict__ B, long sB1, long sB2, int ldb,
    float* __restrict__ C, long sC1, long sC2, int ldc,
    const float* __restrict__ X, int ldx,
    int Kr, int zdiv)
{
    __shared__ __align__(16) __nv_bfloat16 As[2][128][40];  // 80B rows
    __shared__ __align__(16) __nv_bfloat16 Bs[2][128][40];

    const int tid = threadIdx.x;
    const int lane = tid & 31, wid = tid >> 5;
    const int wm = wid & 3, wn = wid >> 2;   // warp tile origin (wm*32, wn*64)

    int z = blockIdx.z;
    int zb = z / zdiv, zh = z - zb * zdiv;
    A += zb * sA1 + zh * sA2;
    B += zb * sB1 + zh * sB2;
    C += zb * sC1 + zh * sC2;
    const long bm = (long)blockIdx.y * 128;
    const long bn = (long)blockIdx.x * 128;

    const int lrow = tid >> 3;        // loader row
    const int lc4  = tid & 7;         // loader float4 col

    float acc[2][8][4];
    #pragma unroll
    for (int i = 0; i < 2; i++)
        #pragma unroll
        for (int j = 0; j < 8; j++)
            #pragma unroll
            for (int q = 0; q < 4; q++) acc[i][j][q] = 0.f;

    float4 ra[4], rb[4];
    const int cpp = Kr >> 5;  // real 32-wide chunks

    // prologue: LDG chunk 0
    #pragma unroll
    for (int j = 0; j < 4; j++) {
        int row = lrow + j * 32;
        ra[j] = *(const float4*)(A + (bm + row) * (long)lda + lc4 * 4);
        rb[j] = *(const float4*)(B + (bn + row) * (long)ldb + lc4 * 4);
    }

    int stage = 0;
    const int r16 = lane & 15, kh8 = (lane >> 4) * 8;

    for (int kc = 0; kc < cpp; ++kc) {
        #pragma unroll
        for (int p = 0; p < 3; ++p) {
            const int s = stage & 1; stage++;
            // STS with per-plane conversion. A: lo iff p==1; B: lo iff p==2.
            #pragma unroll
            for (int j = 0; j < 4; j++) {
                int row = lrow + j * 32;
                uint2 av, bv;
                if (p == 1) { av.x = pack_lo(ra[j].x, ra[j].y); av.y = pack_lo(ra[j].z, ra[j].w); }
                else        { av.x = pack_hi(ra[j].x, ra[j].y); av.y = pack_hi(ra[j].z, ra[j].w); }
                if (p == 2) { bv.x = pack_lo(rb[j].x, rb[j].y); bv.y = pack_lo(rb[j].z, rb[j].w); }
                else        { bv.x = pack_hi(rb[j].x, rb[j].y); bv.y = pack_hi(rb[j].z, rb[j].w); }
                *(uint2*)&As[s][row][lc4 * 4] = av;
                *(uint2*)&Bs[s][row][lc4 * 4] = bv;
            }
            __syncthreads();

            // overlap: LDG next real chunk during last plane's MMA
            if (p == 2 && kc + 1 < cpp) {
                const int k0 = (kc + 1) << 5;
                #pragma unroll
                for (int j = 0; j < 4; j++) {
                    int row = lrow + j * 32;
                    ra[j] = *(const float4*)(A + (bm + row) * (long)lda + k0 + lc4 * 4);
                    rb[j] = *(const float4*)(B + (bn + row) * (long)ldb + k0 + lc4 * 4);
                }
            }

            // MMA over this stage: BK=32 -> two k16 steps
            #pragma unroll
            for (int k16 = 0; k16 < 32; k16 += 16) {
                uint32_t afr[2][4], bfr[8][2];
                #pragma unroll
                for (int mt = 0; mt < 2; mt++)
                    ldmat4(afr[mt], smem_u32(&As[s][wm * 32 + mt * 16 + r16][k16 + kh8]));
                #pragma unroll
                for (int nt4 = 0; nt4 < 4; nt4++) {
                    uint32_t t[4];
                    ldmat4(t, smem_u32(&Bs[s][wn * 64 + nt4 * 16 + r16][k16 + kh8]));
                    bfr[nt4 * 2][0] = t[0]; bfr[nt4 * 2][1] = t[2];
                    bfr[nt4 * 2 + 1][0] = t[1]; bfr[nt4 * 2 + 1][1] = t[3];
                }
                #pragma unroll
                for (int mt = 0; mt < 2; mt++)
                    #pragma unroll
                    for (int nt = 0; nt < 8; nt++)
                        mma16816(acc[mt][nt], afr[mt], bfr[nt]);
            }
            __syncthreads();
        }
    }

    // epilogue
    const long r0 = bm + wm * 32 + (lane >> 2);
    const long c0 = bn + wn * 64 + (lane & 3) * 2;
    const float RS = 0.70710678118654752f;

    #pragma unroll
    for (int mt = 0; mt < 2; mt++) {
        #pragma unroll
        for (int h = 0; h < 2; h++) {
            long row = r0 + mt * 16 + h * 8;
            #pragma unroll
            for (int nt = 0; nt < 8; nt++) {
                long col = c0 + nt * 8;
                float v0 = acc[mt][nt][h * 2], v1 = acc[mt][nt][h * 2 + 1];
                if (MODE == 0) {
                    float2 v; v.x = v0; v.y = v1;
                    *(float2*)(C + row * (long)ldc + col) = v;
                } else if (MODE == 2) {
                    float2 x = *(const float2*)(X + row * (long)ldx + col);
                    float2 v;
                    v.x = (v0 + x.x) * RS; v.y = (v1 + x.y) * RS;
                    *(float2*)(C + row * (long)ldc + col) = v;
                } else {  // vt[((b*8+h)*128+d)*1024 + s]
                    long b = row >> 10, sp = row & 1023;
                    long hh = col >> 7, d = col & 127;
                    float* base = C + (((b << 3) + hh) * 128 + d) * 1024 + sp;
                    base[0] = v0;
                    base[1024] = v1;
                }
            }
        }
    }
}

// ===========================================================================
// Softmax with fused scale + rel-pos bias: softmax(v*alpha + bias) per row.
// ===========================================================================
__global__ void softmax_kernel(float* __restrict__ sc, const float* __restrict__ bias) {
    long row = blockIdx.x;
    float4* p = (float4*)(sc + row * (long)SS);
    const float4* bp = (const float4*)(bias + (row & (long)(HH * SS - 1)) * SS);
    const float alpha = 0.08838834764831845f;  // 1/sqrt(128)
    __shared__ float red[256];
    int t = threadIdx.x;
    float4 v = p[t];
    float4 b4 = bp[t];
    v.x = v.x * alpha + b4.x; v.y = v.y * alpha + b4.y;
    v.z = v.z * alpha + b4.z; v.w = v.w * alpha + b4.w;
    float mx = fmaxf(fmaxf(v.x, v.y), fmaxf(v.z, v.w));
    red[t] = mx; __syncthreads();
    for (int o = 128; o > 0; o >>= 1) {
        if (t < o) red[t] = fmaxf(red[t], red[t + o]);
        __syncthreads();
    }
    float m = red[0];
    __syncthreads();
    v.x = __expf(v.x - m); v.y = __expf(v.y - m);
    v.z = __expf(v.z - m); v.w = __expf(v.w - m);
    float s = v.x + v.y + v.z + v.w;
    red[t] = s; __syncthreads();
    for (int o = 128; o > 0; o >>= 1) {
        if (t < o) red[t] += red[t + o];
        __syncthreads();
    }
    float inv = 1.0f / red[0];
    v.x *= inv; v.y *= inv; v.z *= inv; v.w *= inv;
    p[t] = v;
}

// ===========================================================================
// Launch
// ===========================================================================
extern "C" void kernel_launch(void* const* d_in, const int* in_sizes, int n_in,
                              void* d_out, int out_size) {
    const float* query  = (const float*)d_in[0];
    const float* gain_s = (const float*)d_in[1];
    // d_in[2] = gain_t (unused: time_dim=0)
    const float* qw = (const float*)d_in[3];
    const float* kw = (const float*)d_in[4];
    const float* vw = (const float*)d_in[5];
    const float* ow = (const float*)d_in[6];
    const float* bias = (const float*)d_in[7];
    float* out = (float*)d_out;

    float *wn, *qkv, *sc, *ov;
    cudaGetSymbolAddress((void**)&wn,  g_wn);
    cudaGetSymbolAddress((void**)&qkv, g_qkv);
    cudaGetSymbolAddress((void**)&sc,  g_sc);
    cudaGetSymbolAddress((void**)&ov,  g_ov);
    float* vt = qkv + 2L * MM * EE;  // V^T lives in the V slot

    // 1. Normalize weights
    norm_w_kernel<<<dim3(EE, 4), 256>>>(qw, kw, vw, ow, gain_s);

    // 2a. Q,K projections: qkv[z] = query @ wn[z]^T, z in {0,1}
    mma_gemm<0><<<dim3(EE/128, MM/128, 2), 256>>>(
        query, 0, 0, EE,
        wn, (long)EE*EE, 0, EE,
        qkv, (long)MM*EE, 0, EE,
        nullptr, 0,
        EE, 1);

    // 2b. V projection, written transposed: vt[b][h][d][s]
    mma_gemm<3><<<dim3(EE/128, MM/128, 1), 256>>>(
        query, 0, 0, EE,
        wn + 2L*EE*EE, 0, 0, EE,
        vt, 0, 0, 0,
        nullptr, 0,
        EE, 1);

    // 3. raw scores = Q @ K^T  (z = b*H + h; scale+bias deferred to softmax)
    mma_gemm<0><<<dim3(SS/128, SS/128, BB*HH), 256>>>(
        qkv, (long)SS*EE, (long)HD, EE,                 // Q
        qkv + (long)MM*EE, (long)SS*EE, (long)HD, EE,   // K
        sc, (long)HH*SS*SS, (long)SS*SS, SS,
        nullptr, 0,
        HD, HH);

    // 4. softmax(v/sqrt(hd) + bias), in place
    softmax_kernel<<<BB*HH*SS, 256>>>(sc, bias);

    // 5. O = attn @ V: A = attn [s,t], B = vt [d,t] (K-major, N=128)
    mma_gemm<0><<<dim3(1, SS/128, BB*HH), 256>>>(
        sc, (long)HH*SS*SS, (long)SS*SS, SS,
        vt, (long)HH*HD*SS, (long)HD*SS, SS,
        ov, (long)SS*EE, (long)HD, EE,
        nullptr, 0,
        SS, HH);

    // 6. out = (query + O @ wn_o^T) / sqrt(2)
    mma_gemm<2><<<dim3(EE/128, MM/128, 1), 256>>>(
        ov, 0, 0, EE,
        wn + 3L*EE*EE, 0, 0, EE,
        out, 0, 0, EE,
        query, EE,
        EE, 1);
}

// round 5
// speedup vs baseline: 1.9273x; 1.1386x over previous
#include <cuda_runtime.h>
#include <cuda_bf16.h>
#include <cstdint>
#include <math.h>

#define BB 8
#define SS 1024
#define EE 1024
#define HH 8
#define HD 128
#define MM (BB*SS)

// Scratch (allocation-free: __device__ globals)
__device__ float g_wn[4L * EE * EE];            // normalized weights q,k,v,o
__device__ float g_qkv[3L * MM * EE];           // Q,K projections + V^T
__device__ float g_sc[(long)BB * HH * SS * SS]; // scores / attn (256 MB)
__device__ float g_ov[(long)MM * EE];           // attention output

// ===========================================================================
// helpers
// ===========================================================================
__device__ __forceinline__ uint32_t smem_u32(const void* p) {
    uint32_t a;
    asm("{ .reg .u64 t; cvta.to.shared.u64 t, %1; cvt.u32.u64 %0, t; }"
        : "=r"(a) : "l"(p));
    return a;
}
__device__ __forceinline__ void ldmat4(uint32_t* r, uint32_t addr) {
    asm volatile("ldmatrix.sync.aligned.m8n8.x4.shared.b16 {%0,%1,%2,%3}, [%4];"
                 : "=r"(r[0]), "=r"(r[1]), "=r"(r[2]), "=r"(r[3]) : "r"(addr));
}
__device__ __forceinline__ void mma16816(float* c, const uint32_t* a, const uint32_t* b) {
    asm volatile(
        "mma.sync.aligned.m16n8k16.row.col.f32.bf16.bf16.f32 "
        "{%0,%1,%2,%3}, {%4,%5,%6,%7}, {%8,%9}, {%0,%1,%2,%3};"
        : "+f"(c[0]), "+f"(c[1]), "+f"(c[2]), "+f"(c[3])
        : "r"(a[0]), "r"(a[1]), "r"(a[2]), "r"(a[3]), "r"(b[0]), "r"(b[1]));
}
__device__ __forceinline__ uint32_t pack_hi(float x, float y) {
    float2 f; f.x = x; f.y = y;
    __nv_bfloat162 t = __float22bfloat162_rn(f);
    return *(uint32_t*)&t;
}
__device__ __forceinline__ uint32_t pack_lo(float x, float y) {
    __nv_bfloat16 hx = __float2bfloat16(x), hy = __float2bfloat16(y);
    float2 f;
    f.x = x - __bfloat162float(hx);
    f.y = y - __bfloat162float(hy);
    __nv_bfloat162 t = __float22bfloat162_rn(f);
    return *(uint32_t*)&t;
}

// ===========================================================================
// Weight normalization: wn = w * gain / (sqrt(fan_in)*EPS + ||row||)
// ===========================================================================
__global__ void norm_w_kernel(const float* __restrict__ qw,
                              const float* __restrict__ kw,
                              const float* __restrict__ vw,
                              const float* __restrict__ ow,
                              const float* __restrict__ gain) {
    int mat = blockIdx.y;
    int row = blockIdx.x;
    const float* w = (mat == 0) ? qw : (mat == 1) ? kw : (mat == 2) ? vw : ow;
    const float* wr = w + (long)row * EE;
    __shared__ float red[256];
    float s = 0.f;
    for (int i = threadIdx.x; i < EE; i += 256) { float v = wr[i]; s += v * v; }
    red[threadIdx.x] = s; __syncthreads();
    for (int o = 128; o > 0; o >>= 1) {
        if (threadIdx.x < o) red[threadIdx.x] += red[threadIdx.x + o];
        __syncthreads();
    }
    float n = sqrtf(red[0]);
    float scale = gain[0] / (32.0f * 1e-4f + n);
    float* out = g_wn + (long)mat * EE * EE + (long)row * EE;
    for (int i = threadIdx.x; i < EE; i += 256) out[i] = wr[i] * scale;
}

// ===========================================================================
// mma.sync GEMM, split-bf16 (bf16x3): D = Ah Bh^T + Al Bh^T + Ah Bl^T.
// 4-plane scheme: per 32-wide fp32 K chunk, store Ah/Al/Bh/Bl ONCE, then run
// the 3 MMA passes out of those planes (Ah/Bh fragments reused in regs).
// 2-stage smem, ONE __syncthreads per chunk; next-chunk LDG overlaps MMA.
// CTA tile 128x128, 8 warps (4x2) of 32x64.
// MODE 0: C = acc
// MODE 2: C = (acc + X) * (1/sqrt(2))   (mp_sum residual, t=0.5)
// MODE 3: transpose write: C as vt[b][h][d][s]
// ===========================================================================
#define PLN 5120                // plane: 128 rows x 40 elems (80B rows)
#define SMEM_BYTES (2*4*PLN*2)  // 81920

template<int MODE>
__global__ __launch_bounds__(256) void mma_gemm(
    const float* __restrict__ A, long sA1, long sA2, int lda,
    const float* __restrict__ B, long sB1, long sB2, int ldb,
    float* __restrict__ C, long sC1, long sC2, int ldc,
    const float* __restrict__ X, int ldx,
    int Kr, int zdiv)
{
    extern __shared__ __nv_bfloat16 smp[];   // [2][4][128][40]

    const int tid = threadIdx.x;
    const int lane = tid & 31, wid = tid >> 5;
    const int wm = wid & 3, wn = wid >> 2;   // warp tile origin (wm*32, wn*64)

    int z = blockIdx.z;
    int zb = z / zdiv, zh = z - zb * zdiv;
    A += zb * sA1 + zh * sA2;
    B += zb * sB1 + zh * sB2;
    C += zb * sC1 + zh * sC2;
    const long bm = (long)blockIdx.y * 128;
    const long bn = (long)blockIdx.x * 128;

    const int lrow = tid >> 3;        // loader row
    const int lc4  = tid & 7;         // loader float4 col

    float acc[2][8][4];
    #pragma unroll
    for (int i = 0; i < 2; i++)
        #pragma unroll
        for (int j = 0; j < 8; j++)
            #pragma unroll
            for (int q = 0; q < 4; q++) acc[i][j][q] = 0.f;

    float4 ra[4], rb[4];
    const int cpp = Kr >> 5;  // 32-wide fp32 chunks

    // prologue: LDG chunk 0
    #pragma unroll
    for (int j = 0; j < 4; j++) {
        int row = lrow + j * 32;
        ra[j] = *(const float4*)(A + (bm + row) * (long)lda + lc4 * 4);
        rb[j] = *(const float4*)(B + (bn + row) * (long)ldb + lc4 * 4);
    }

    const int r16 = lane & 15, kh8 = (lane >> 4) * 8;

    for (int kc = 0; kc < cpp; ++kc) {
        const int s = kc & 1;
        __nv_bfloat16* pAh = smp + (s * 4 + 0) * PLN;
        __nv_bfloat16* pAl = smp + (s * 4 + 1) * PLN;
        __nv_bfloat16* pBh = smp + (s * 4 + 2) * PLN;
        __nv_bfloat16* pBl = smp + (s * 4 + 3) * PLN;

        // STS all 4 planes once
        #pragma unroll
        for (int j = 0; j < 4; j++) {
            int row = lrow + j * 32;
            int off = row * 40 + lc4 * 4;
            uint2 v;
            v.x = pack_hi(ra[j].x, ra[j].y); v.y = pack_hi(ra[j].z, ra[j].w);
            *(uint2*)&pAh[off] = v;
            v.x = pack_lo(ra[j].x, ra[j].y); v.y = pack_lo(ra[j].z, ra[j].w);
            *(uint2*)&pAl[off] = v;
            v.x = pack_hi(rb[j].x, rb[j].y); v.y = pack_hi(rb[j].z, rb[j].w);
            *(uint2*)&pBh[off] = v;
            v.x = pack_lo(rb[j].x, rb[j].y); v.y = pack_lo(rb[j].z, rb[j].w);
            *(uint2*)&pBl[off] = v;
        }
        __syncthreads();

        // prefetch next chunk (overlaps MMA below)
        if (kc + 1 < cpp) {
            const int k0 = (kc + 1) << 5;
            #pragma unroll
            for (int j = 0; j < 4; j++) {
                int row = lrow + j * 32;
                ra[j] = *(const float4*)(A + (bm + row) * (long)lda + k0 + lc4 * 4);
                rb[j] = *(const float4*)(B + (bn + row) * (long)ldb + k0 + lc4 * 4);
            }
        }

        // MMA: 2 k16 steps x 3 plane-pairs
        #pragma unroll
        for (int k16 = 0; k16 < 32; k16 += 16) {
            uint32_t ah[2][4], al[2][4], bh[8][2], bl[8][2];
            const int arow = wm * 32 + r16;
            const int brow = wn * 64 + r16;
            #pragma unroll
            for (int mt = 0; mt < 2; mt++)
                ldmat4(ah[mt], smem_u32(&pAh[(arow + mt * 16) * 40 + k16 + kh8]));
            #pragma unroll
            for (int nt4 = 0; nt4 < 4; nt4++) {
                uint32_t t[4];
                ldmat4(t, smem_u32(&pBh[(brow + nt4 * 16) * 40 + k16 + kh8]));
                bh[nt4 * 2][0] = t[0]; bh[nt4 * 2][1] = t[2];
                bh[nt4 * 2 + 1][0] = t[1]; bh[nt4 * 2 + 1][1] = t[3];
            }
            #pragma unroll
            for (int mt = 0; mt < 2; mt++)
                #pragma unroll
                for (int nt = 0; nt < 8; nt++)
                    mma16816(acc[mt][nt], ah[mt], bh[nt]);

            #pragma unroll
            for (int mt = 0; mt < 2; mt++)
                ldmat4(al[mt], smem_u32(&pAl[(arow + mt * 16) * 40 + k16 + kh8]));
            #pragma unroll
            for (int mt = 0; mt < 2; mt++)
                #pragma unroll
                for (int nt = 0; nt < 8; nt++)
                    mma16816(acc[mt][nt], al[mt], bh[nt]);

            #pragma unroll
            for (int nt4 = 0; nt4 < 4; nt4++) {
                uint32_t t[4];
                ldmat4(t, smem_u32(&pBl[(brow + nt4 * 16) * 40 + k16 + kh8]));
                bl[nt4 * 2][0] = t[0]; bl[nt4 * 2][1] = t[2];
                bl[nt4 * 2 + 1][0] = t[1]; bl[nt4 * 2 + 1][1] = t[3];
            }
            #pragma unroll
            for (int mt = 0; mt < 2; mt++)
                #pragma unroll
                for (int nt = 0; nt < 8; nt++)
                    mma16816(acc[mt][nt], ah[mt], bl[nt]);
        }
    }

    // epilogue
    const long r0 = bm + wm * 32 + (lane >> 2);
    const long c0 = bn + wn * 64 + (lane & 3) * 2;
    const float RS = 0.70710678118654752f;

    #pragma unroll
    for (int mt = 0; mt < 2; mt++) {
        #pragma unroll
        for (int h = 0; h < 2; h++) {
            long row = r0 + mt * 16 + h * 8;
            #pragma unroll
            for (int nt = 0; nt < 8; nt++) {
                long col = c0 + nt * 8;
                float v0 = acc[mt][nt][h * 2], v1 = acc[mt][nt][h * 2 + 1];
                if (MODE == 0) {
                    float2 v; v.x = v0; v.y = v1;
                    *(float2*)(C + row * (long)ldc + col) = v;
                } else if (MODE == 2) {
                    float2 x = *(const float2*)(X + row * (long)ldx + col);
                    float2 v;
                    v.x = (v0 + x.x) * RS; v.y = (v1 + x.y) * RS;
                    *(float2*)(C + row * (long)ldc + col) = v;
                } else {  // vt[((b*8+h)*128+d)*1024 + s]
                    long b = row >> 10, sp = row & 1023;
                    long hh = col >> 7, d = col & 127;
                    float* base = C + (((b << 3) + hh) * 128 + d) * 1024 + sp;
                    base[0] = v0;
                    base[1024] = v1;
                }
            }
        }
    }
}

// ===========================================================================
// Softmax with fused scale + rel-pos bias: softmax(v*alpha + bias) per row.
// ===========================================================================
__global__ void softmax_kernel(float* __restrict__ sc, const float* __restrict__ bias) {
    long row = blockIdx.x;
    float4* p = (float4*)(sc + row * (long)SS);
    const float4* bp = (const float4*)(bias + (row & (long)(HH * SS - 1)) * SS);
    const float alpha = 0.08838834764831845f;  // 1/sqrt(128)
    __shared__ float red[256];
    int t = threadIdx.x;
    float4 v = p[t];
    float4 b4 = bp[t];
    v.x = v.x * alpha + b4.x; v.y = v.y * alpha + b4.y;
    v.z = v.z * alpha + b4.z; v.w = v.w * alpha + b4.w;
    float mx = fmaxf(fmaxf(v.x, v.y), fmaxf(v.z, v.w));
    red[t] = mx; __syncthreads();
    for (int o = 128; o > 0; o >>= 1) {
        if (t < o) red[t] = fmaxf(red[t], red[t + o]);
        __syncthreads();
    }
    float m = red[0];
    __syncthreads();
    v.x = __expf(v.x - m); v.y = __expf(v.y - m);
    v.z = __expf(v.z - m); v.w = __expf(v.w - m);
    float s = v.x + v.y + v.z + v.w;
    red[t] = s; __syncthreads();
    for (int o = 128; o > 0; o >>= 1) {
        if (t < o) red[t] += red[t + o];
        __syncthreads();
    }
    float inv = 1.0f / red[0];
    v.x *= inv; v.y *= inv; v.z *= inv; v.w *= inv;
    p[t] = v;
}

// ===========================================================================
// Launch
// ===========================================================================
extern "C" void kernel_launch(void* const* d_in, const int* in_sizes, int n_in,
                              void* d_out, int out_size) {
    const float* query  = (const float*)d_in[0];
    const float* gain_s = (const float*)d_in[1];
    // d_in[2] = gain_t (unused: time_dim=0)
    const float* qw = (const float*)d_in[3];
    const float* kw = (const float*)d_in[4];
    const float* vw = (const float*)d_in[5];
    const float* ow = (const float*)d_in[6];
    const float* bias = (const float*)d_in[7];
    float* out = (float*)d_out;

    float *wn, *qkv, *sc, *ov;
    cudaGetSymbolAddress((void**)&wn,  g_wn);
    cudaGetSymbolAddress((void**)&qkv, g_qkv);
    cudaGetSymbolAddress((void**)&sc,  g_sc);
    cudaGetSymbolAddress((void**)&ov,  g_ov);
    float* vt = qkv + 2L * MM * EE;  // V^T lives in the V slot

    cudaFuncSetAttribute(mma_gemm<0>, cudaFuncAttributeMaxDynamicSharedMemorySize, SMEM_BYTES);
    cudaFuncSetAttribute(mma_gemm<2>, cudaFuncAttributeMaxDynamicSharedMemorySize, SMEM_BYTES);
    cudaFuncSetAttribute(mma_gemm<3>, cudaFuncAttributeMaxDynamicSharedMemorySize, SMEM_BYTES);

    // 1. Normalize weights
    norm_w_kernel<<<dim3(EE, 4), 256>>>(qw, kw, vw, ow, gain_s);

    // 2a. Q,K projections: qkv[z] = query @ wn[z]^T, z in {0,1}
    mma_gemm<0><<<dim3(EE/128, MM/128, 2), 256, SMEM_BYTES>>>(
        query, 0, 0, EE,
        wn, (long)EE*EE, 0, EE,
        qkv, (long)MM*EE, 0, EE,
        nullptr, 0,
        EE, 1);

    // 2b. V projection, written transposed: vt[b][h][d][s]
    mma_gemm<3><<<dim3(EE/128, MM/128, 1), 256, SMEM_BYTES>>>(
        query, 0, 0, EE,
        wn + 2L*EE*EE, 0, 0, EE,
        vt, 0, 0, 0,
        nullptr, 0,
        EE, 1);

    // 3. raw scores = Q @ K^T  (z = b*H + h; scale+bias deferred to softmax)
    mma_gemm<0><<<dim3(SS/128, SS/128, BB*HH), 256, SMEM_BYTES>>>(
        qkv, (long)SS*EE, (long)HD, EE,                 // Q
        qkv + (long)MM*EE, (long)SS*EE, (long)HD, EE,   // K
        sc, (long)HH*SS*SS, (long)SS*SS, SS,
        nullptr, 0,
        HD, HH);

    // 4. softmax(v/sqrt(hd) + bias), in place
    softmax_kernel<<<BB*HH*SS, 256>>>(sc, bias);

    // 5. O = attn @ V: A = attn [s,t], B = vt [d,t] (K-major, N=128)
    mma_gemm<0><<<dim3(1, SS/128, BB*HH), 256, SMEM_BYTES>>>(
        sc, (long)HH*SS*SS, (long)SS*SS, SS,
        vt, (long)HH*HD*SS, (long)HD*SS, SS,
        ov, (long)SS*EE, (long)HD, EE,
        nullptr, 0,
        SS, HH);

    // 6. out = (query + O @ wn_o^T) / sqrt(2)
    mma_gemm<2><<<dim3(EE/128, MM/128, 1), 256, SMEM_BYTES>>>(
        ov, 0, 0, EE,
        wn + 3L*EE*EE, 0, 0, EE,
        out, 0, 0, EE,
        query, EE,
        EE, 1);
}

// round 6
// speedup vs baseline: 2.3090x; 1.1981x over previous
#include <cuda_runtime.h>
#include <cuda_bf16.h>
#include <cstdint>
#include <math.h>

#define BB 8
#define SS 1024
#define EE 1024
#define HH 8
#define HD 128
#define MM (BB*SS)

// Scratch (allocation-free: __device__ globals), all split-bf16 hi/lo planes
__device__ __nv_bfloat16 g_wnh[4L * EE * EE], g_wnl[4L * EE * EE]; // weights
__device__ __nv_bfloat16 g_xh[(long)MM * EE], g_xl[(long)MM * EE]; // query
__device__ __nv_bfloat16 g_ph[2L * MM * EE],  g_pl[2L * MM * EE];  // Q,K
__device__ __nv_bfloat16 g_vth[(long)MM * EE], g_vtl[(long)MM * EE]; // V^T
__device__ float g_sc[(long)BB * HH * SS * SS];                    // scores fp32
__device__ __nv_bfloat16 g_ah[(long)BB * HH * SS * SS];            // attn hi
__device__ __nv_bfloat16 g_al[(long)BB * HH * SS * SS];            // attn lo
__device__ __nv_bfloat16 g_ovh[(long)MM * EE], g_ovl[(long)MM * EE]; // attn out

// ===========================================================================
// helpers
// ===========================================================================
__device__ __forceinline__ uint32_t smem_u32(const void* p) {
    uint32_t a;
    asm("{ .reg .u64 t; cvta.to.shared.u64 t, %1; cvt.u32.u64 %0, t; }"
        : "=r"(a) : "l"(p));
    return a;
}
__device__ __forceinline__ void ldmat4(uint32_t* r, uint32_t addr) {
    asm volatile("ldmatrix.sync.aligned.m8n8.x4.shared.b16 {%0,%1,%2,%3}, [%4];"
                 : "=r"(r[0]), "=r"(r[1]), "=r"(r[2]), "=r"(r[3]) : "r"(addr));
}
__device__ __forceinline__ void mma16816(float* c, const uint32_t* a, const uint32_t* b) {
    asm volatile(
        "mma.sync.aligned.m16n8k16.row.col.f32.bf16.bf16.f32 "
        "{%0,%1,%2,%3}, {%4,%5,%6,%7}, {%8,%9}, {%0,%1,%2,%3};"
        : "+f"(c[0]), "+f"(c[1]), "+f"(c[2]), "+f"(c[3])
        : "r"(a[0]), "r"(a[1]), "r"(a[2]), "r"(a[3]), "r"(b[0]), "r"(b[1]));
}
__device__ __forceinline__ void cpa16(uint32_t dst, const void* src) {
    asm volatile("cp.async.cg.shared.global [%0], [%1], 16;"
                 :: "r"(dst), "l"(src) : "memory");
}
__device__ __forceinline__ void cp_commit() {
    asm volatile("cp.async.commit_group;" ::: "memory");
}
template<int N>
__device__ __forceinline__ void cp_wait() {
    asm volatile("cp.async.wait_group %0;" :: "n"(N) : "memory");
}
__device__ __forceinline__ void split2(float x, float y,
                                       __nv_bfloat162& hi, __nv_bfloat162& lo) {
    hi.x = __float2bfloat16(x); hi.y = __float2bfloat16(y);
    lo.x = __float2bfloat16(x - __bfloat162float(hi.x));
    lo.y = __float2bfloat16(y - __bfloat162float(hi.y));
}

// swizzled byte offset of (row, elem) in a packed [128][32] bf16 tile plane
__device__ __forceinline__ uint32_t tswz(int r, int e) {
    return (uint32_t)(r * 64 + ((((e >> 3) ^ (r >> 1)) & 3) << 4) + (e & 7) * 2);
}

// ===========================================================================
// Weight normalization -> split bf16 planes
// ===========================================================================
__global__ void norm_w_kernel(const float* __restrict__ qw,
                              const float* __restrict__ kw,
                              const float* __restrict__ vw,
                              const float* __restrict__ ow,
                              const float* __restrict__ gain) {
    int mat = blockIdx.y;
    int row = blockIdx.x;
    const float* w = (mat == 0) ? qw : (mat == 1) ? kw : (mat == 2) ? vw : ow;
    const float* wr = w + (long)row * EE;
    __shared__ float red[256];
    float s = 0.f;
    for (int i = threadIdx.x; i < EE; i += 256) { float v = wr[i]; s += v * v; }
    red[threadIdx.x] = s; __syncthreads();
    for (int o = 128; o > 0; o >>= 1) {
        if (threadIdx.x < o) red[threadIdx.x] += red[threadIdx.x + o];
        __syncthreads();
    }
    float n = sqrtf(red[0]);
    float scale = gain[0] / (32.0f * 1e-4f + n);
    long base = (long)mat * EE * EE + (long)row * EE;
    for (int i = threadIdx.x * 2; i < EE; i += 512) {
        __nv_bfloat162 hi, lo;
        split2(wr[i] * scale, wr[i + 1] * scale, hi, lo);
        *(__nv_bfloat162*)(g_wnh + base + i) = hi;
        *(__nv_bfloat162*)(g_wnl + base + i) = lo;
    }
}

// ===========================================================================
// query fp32 -> split bf16 planes
// ===========================================================================
__global__ void convert_x_kernel(const float* __restrict__ x) {
    long i = ((long)blockIdx.x * 256 + threadIdx.x) * 4;
    float4 v = *(const float4*)(x + i);
    __nv_bfloat162 h0, l0, h1, l1;
    split2(v.x, v.y, h0, l0);
    split2(v.z, v.w, h1, l1);
    *(__nv_bfloat162*)(g_xh + i) = h0; *(__nv_bfloat162*)(g_xh + i + 2) = h1;
    *(__nv_bfloat162*)(g_xl + i) = l0; *(__nv_bfloat162*)(g_xl + i + 2) = l1;
}

// ===========================================================================
// bf16 split GEMM: D[M,N] = (Ah+Al)[M,K] @ (Bh+Bl)[N,K]^T, 3 passes
// (AhBh + AlBh + AhBl). All operands pre-split bf16 planes in global.
// 3-stage cp.async pipeline, packed 64B rows + XOR chunk swizzle,
// CTA 128x128, 8 warps (4x2) of 32x64, BK=32. 2 CTAs/SM.
// MODE 0: C0 = fp32 acc             (scores)
// MODE 1: split write: C0/C1 = hi/lo bf16 planes  (Q,K / attn@V)
// MODE 2: C0 = (acc + X) / sqrt(2), fp32          (residual out)
// MODE 3: transpose split write: vt[b][h][d][s] hi/lo
// ===========================================================================
#define STG_BYTES 32768           // 4 planes x 8KB
#define SMEM_BYTES (3*STG_BYTES)  // 98304

template<int MODE>
__global__ __launch_bounds__(256, 2) void mma_gemm(
    const __nv_bfloat16* __restrict__ Ah, const __nv_bfloat16* __restrict__ Al,
    long sA1, long sA2, int lda,
    const __nv_bfloat16* __restrict__ Bh, const __nv_bfloat16* __restrict__ Bl,
    long sB1, long sB2, int ldb,
    void* C0v, void* C1v, long sC1, long sC2, int ldc,
    const float* __restrict__ X, int ldx,
    int Kr, int zdiv)
{
    extern __shared__ char smp[];
    const uint32_t smb = smem_u32(smp);

    const int tid = threadIdx.x;
    const int lane = tid & 31, wid = tid >> 5;
    const int wm = wid & 3, wn = wid >> 2;

    int z = blockIdx.z;
    int zb = z / zdiv, zh = z - zb * zdiv;
    Ah += zb * sA1 + zh * sA2;  Al += zb * sA1 + zh * sA2;
    Bh += zb * sB1 + zh * sB2;  Bl += zb * sB1 + zh * sB2;
    const long coff = zb * sC1 + zh * sC2;
    const long bm = (long)blockIdx.y * 128;
    const long bn = (long)blockIdx.x * 128;

    const int lrow = tid >> 1;          // 0..127
    const int lc0 = (tid & 1) * 2;      // first of 2 chunks
    const uint32_t lsw = (uint32_t)((lrow >> 1) & 3);
    const uint32_t lso = (uint32_t)(lrow * 64);

    const __nv_bfloat16* gAh = Ah + (bm + lrow) * (long)lda;
    const __nv_bfloat16* gAl = Al + (bm + lrow) * (long)lda;
    const __nv_bfloat16* gBh = Bh + (bn + lrow) * (long)ldb;
    const __nv_bfloat16* gBl = Bl + (bn + lrow) * (long)ldb;

    float acc[2][8][4];
    #pragma unroll
    for (int i = 0; i < 2; i++)
        #pragma unroll
        for (int j = 0; j < 8; j++)
            #pragma unroll
            for (int q = 0; q < 4; q++) acc[i][j][q] = 0.f;

    const int cpp = Kr >> 5;

    auto issue = [&](int chunk) {
        const uint32_t base = smb + (chunk % 3) * STG_BYTES;
        const int k0 = chunk << 5;
        #pragma unroll
        for (int j = 0; j < 2; j++) {
            int c = lc0 + j;
            uint32_t off = lso + (((uint32_t)c ^ lsw) << 4);
            cpa16(base + off,         gAh + k0 + c * 8);
            cpa16(base + 8192 + off,  gAl + k0 + c * 8);
            cpa16(base + 16384 + off, gBh + k0 + c * 8);
            cpa16(base + 24576 + off, gBl + k0 + c * 8);
        }
    };

    // prologue: 2 stages in flight
    issue(0); cp_commit();
    if (cpp > 1) issue(1);
    cp_commit();

    const int r16 = lane & 15, kh8 = (lane >> 4) * 8;
    const int arow = wm * 32 + r16;
    const int brow = wn * 64 + r16;

    for (int kc = 0; kc < cpp; ++kc) {
        cp_wait<1>();
        __syncthreads();
        if (kc + 2 < cpp) issue(kc + 2);
        cp_commit();

        const uint32_t sb = smb + (kc % 3) * STG_BYTES;
        #pragma unroll
        for (int k16 = 0; k16 < 32; k16 += 16) {
            const int e = k16 + kh8;
            uint32_t ah[2][4], bh[8][2];
            #pragma unroll
            for (int mt = 0; mt < 2; mt++)
                ldmat4(ah[mt], sb + tswz(arow + mt * 16, e));
            #pragma unroll
            for (int nt4 = 0; nt4 < 4; nt4++) {
                uint32_t t[4];
                ldmat4(t, sb + 16384 + tswz(brow + nt4 * 16, e));
                bh[nt4 * 2][0] = t[0]; bh[nt4 * 2][1] = t[2];
                bh[nt4 * 2 + 1][0] = t[1]; bh[nt4 * 2 + 1][1] = t[3];
            }
            #pragma unroll
            for (int mt = 0; mt < 2; mt++)
                #pragma unroll
                for (int nt = 0; nt < 8; nt++)
                    mma16816(acc[mt][nt], ah[mt], bh[nt]);

            uint32_t al[2][4];
            #pragma unroll
            for (int mt = 0; mt < 2; mt++)
                ldmat4(al[mt], sb + 8192 + tswz(arow + mt * 16, e));
            #pragma unroll
            for (int mt = 0; mt < 2; mt++)
                #pragma unroll
                for (int nt = 0; nt < 8; nt++)
                    mma16816(acc[mt][nt], al[mt], bh[nt]);

            uint32_t bl[8][2];
            #pragma unroll
            for (int nt4 = 0; nt4 < 4; nt4++) {
                uint32_t t[4];
                ldmat4(t, sb + 24576 + tswz(brow + nt4 * 16, e));
                bl[nt4 * 2][0] = t[0]; bl[nt4 * 2][1] = t[2];
                bl[nt4 * 2 + 1][0] = t[1]; bl[nt4 * 2 + 1][1] = t[3];
            }
            #pragma unroll
            for (int mt = 0; mt < 2; mt++)
                #pragma unroll
                for (int nt = 0; nt < 8; nt++)
                    mma16816(acc[mt][nt], ah[mt], bl[nt]);
        }
        __syncthreads();
    }

    // epilogue
    const long r0 = bm + wm * 32 + (lane >> 2);
    const long c0 = bn + wn * 64 + (lane & 3) * 2;
    const float RS = 0.70710678118654752f;

    #pragma unroll
    for (int mt = 0; mt < 2; mt++) {
        #pragma unroll
        for (int h = 0; h < 2; h++) {
            long row = r0 + mt * 16 + h * 8;
            #pragma unroll
            for (int nt = 0; nt < 8; nt++) {
                long col = c0 + nt * 8;
                float v0 = acc[mt][nt][h * 2], v1 = acc[mt][nt][h * 2 + 1];
                if (MODE == 0) {
                    float* C = (float*)C0v + coff;
                    float2 v; v.x = v0; v.y = v1;
                    *(float2*)(C + row * (long)ldc + col) = v;
                } else if (MODE == 1) {
                    __nv_bfloat16* Ch = (__nv_bfloat16*)C0v + coff;
                    __nv_bfloat16* Cl = (__nv_bfloat16*)C1v + coff;
                    __nv_bfloat162 hi, lo;
                    split2(v0, v1, hi, lo);
                    *(__nv_bfloat162*)(Ch + row * (long)ldc + col) = hi;
                    *(__nv_bfloat162*)(Cl + row * (long)ldc + col) = lo;
                } else if (MODE == 2) {
                    float* C = (float*)C0v + coff;
                    float2 x = *(const float2*)(X + row * (long)ldx + col);
                    float2 v;
                    v.x = (v0 + x.x) * RS; v.y = (v1 + x.y) * RS;
                    *(float2*)(C + row * (long)ldc + col) = v;
                } else {  // MODE 3: vt[((b*8+h)*128+d)*1024 + s] split
                    __nv_bfloat16* Ch = (__nv_bfloat16*)C0v;
                    __nv_bfloat16* Cl = (__nv_bfloat16*)C1v;
                    long b = row >> 10, sp = row & 1023;
                    long hh = col >> 7, d = col & 127;
                    long base = (((b << 3) + hh) * 128 + d) * 1024 + sp;
                    __nv_bfloat162 hi, lo;
                    split2(v0, v1, hi, lo);
                    Ch[base] = hi.x; Ch[base + 1024] = hi.y;
                    Cl[base] = lo.x; Cl[base + 1024] = lo.y;
                }
            }
        }
    }
}

// ===========================================================================
// Softmax: softmax(v*alpha + bias) per row, fp32 in -> split bf16 planes out
// ===========================================================================
__global__ void softmax_kernel(const float* __restrict__ sc,
                               const float* __restrict__ bias) {
    long row = blockIdx.x;
    const float4* p = (const float4*)(sc + row * (long)SS);
    const float4* bp = (const float4*)(bias + (row & (long)(HH * SS - 1)) * SS);
    const float alpha = 0.08838834764831845f;  // 1/sqrt(128)
    __shared__ float red[256];
    int t = threadIdx.x;
    float4 v = p[t];
    float4 b4 = bp[t];
    v.x = v.x * alpha + b4.x; v.y = v.y * alpha + b4.y;
    v.z = v.z * alpha + b4.z; v.w = v.w * alpha + b4.w;
    float mx = fmaxf(fmaxf(v.x, v.y), fmaxf(v.z, v.w));
    red[t] = mx; __syncthreads();
    for (int o = 128; o > 0; o >>= 1) {
        if (t < o) red[t] = fmaxf(red[t], red[t + o]);
        __syncthreads();
    }
    float m = red[0];
    __syncthreads();
    v.x = __expf(v.x - m); v.y = __expf(v.y - m);
    v.z = __expf(v.z - m); v.w = __expf(v.w - m);
    float s = v.x + v.y + v.z + v.w;
    red[t] = s; __syncthreads();
    for (int o = 128; o > 0; o >>= 1) {
        if (t < o) red[t] += red[t + o];
        __syncthreads();
    }
    float inv = 1.0f / red[0];
    v.x *= inv; v.y *= inv; v.z *= inv; v.w *= inv;
    long i = row * (long)SS + t * 4;
    __nv_bfloat162 h0, l0, h1, l1;
    split2(v.x, v.y, h0, l0);
    split2(v.z, v.w, h1, l1);
    *(__nv_bfloat162*)(g_ah + i) = h0; *(__nv_bfloat162*)(g_ah + i + 2) = h1;
    *(__nv_bfloat162*)(g_al + i) = l0; *(__nv_bfloat162*)(g_al + i + 2) = l1;
}

// ===========================================================================
// Launch
// ===========================================================================
extern "C" void kernel_launch(void* const* d_in, const int* in_sizes, int n_in,
                              void* d_out, int out_size) {
    const float* query  = (const float*)d_in[0];
    const float* gain_s = (const float*)d_in[1];
    // d_in[2] = gain_t (unused: time_dim=0)
    const float* qw = (const float*)d_in[3];
    const float* kw = (const float*)d_in[4];
    const float* vw = (const float*)d_in[5];
    const float* ow = (const float*)d_in[6];
    const float* bias = (const float*)d_in[7];
    float* out = (float*)d_out;

    __nv_bfloat16 *wnh, *wnl, *xh, *xl, *ph, *pl, *vth, *vtl, *ah, *al, *ovh, *ovl;
    float *sc;
    cudaGetSymbolAddress((void**)&wnh, g_wnh); cudaGetSymbolAddress((void**)&wnl, g_wnl);
    cudaGetSymbolAddress((void**)&xh,  g_xh);  cudaGetSymbolAddress((void**)&xl,  g_xl);
    cudaGetSymbolAddress((void**)&ph,  g_ph);  cudaGetSymbolAddress((void**)&pl,  g_pl);
    cudaGetSymbolAddress((void**)&vth, g_vth); cudaGetSymbolAddress((void**)&vtl, g_vtl);
    cudaGetSymbolAddress((void**)&ah,  g_ah);  cudaGetSymbolAddress((void**)&al,  g_al);
    cudaGetSymbolAddress((void**)&ovh, g_ovh); cudaGetSymbolAddress((void**)&ovl, g_ovl);
    cudaGetSymbolAddress((void**)&sc,  g_sc);

    cudaFuncSetAttribute(mma_gemm<0>, cudaFuncAttributeMaxDynamicSharedMemorySize, SMEM_BYTES);
    cudaFuncSetAttribute(mma_gemm<1>, cudaFuncAttributeMaxDynamicSharedMemorySize, SMEM_BYTES);
    cudaFuncSetAttribute(mma_gemm<2>, cudaFuncAttributeMaxDynamicSharedMemorySize, SMEM_BYTES);
    cudaFuncSetAttribute(mma_gemm<3>, cudaFuncAttributeMaxDynamicSharedMemorySize, SMEM_BYTES);

    // 1. Normalize weights -> split planes; convert query -> split planes
    norm_w_kernel<<<dim3(EE, 4), 256>>>(qw, kw, vw, ow, gain_s);
    convert_x_kernel<<<(long)MM * EE / 1024, 256>>>(query);

    // 2a. Q,K projections -> split planes (z: 0=Q, 1=K)
    mma_gemm<1><<<dim3(EE/128, MM/128, 2), 256, SMEM_BYTES>>>(
        xh, xl, 0, 0, EE,
        wnh, wnl, (long)EE*EE, 0, EE,
        ph, pl, (long)MM*EE, 0, EE,
        nullptr, 0, EE, 1);

    // 2b. V projection -> transposed split planes vt[b][h][d][s]
    mma_gemm<3><<<dim3(EE/128, MM/128, 1), 256, SMEM_BYTES>>>(
        xh, xl, 0, 0, EE,
        wnh + 2L*EE*EE, wnl + 2L*EE*EE, 0, 0, EE,
        vth, vtl, 0, 0, 0,
        nullptr, 0, EE, 1);

    // 3. raw scores = Q @ K^T (fp32; scale+bias deferred to softmax)
    mma_gemm<0><<<dim3(SS/128, SS/128, BB*HH), 256, SMEM_BYTES>>>(
        ph, pl, (long)SS*EE, (long)HD, EE,
        ph + (long)MM*EE, pl + (long)MM*EE, (long)SS*EE, (long)HD, EE,
        sc, nullptr, (long)HH*SS*SS, (long)SS*SS, SS,
        nullptr, 0, HD, HH);

    // 4. softmax(v/sqrt(hd) + bias) -> attn split planes
    softmax_kernel<<<BB*HH*SS, 256>>>(sc, bias);

    // 5. O = attn @ V -> split planes (A: [s][t], B: vt [d][t], N=128)
    mma_gemm<1><<<dim3(1, SS/128, BB*HH), 256, SMEM_BYTES>>>(
        ah, al, (long)HH*SS*SS, (long)SS*SS, SS,
        vth, vtl, (long)HH*HD*SS, (long)HD*SS, SS,
        ovh, ovl, (long)SS*EE, (long)HD, EE,
        nullptr, 0, SS, HH);

    // 6. out = (query + OV @ wn_o^T) / sqrt(2)
    mma_gemm<2><<<dim3(EE/128, MM/128, 1), 256, SMEM_BYTES>>>(
        ovh, ovl, 0, 0, EE,
        wnh + 3L*EE*EE, wnl + 3L*EE*EE, 0, 0, EE,
        out, nullptr, 0, 0, EE,
        query, EE, EE, 1);
}